// round 15
// baseline (speedup 1.0000x reference)
#include <cuda_runtime.h>

#define BS      16
#define NANCH   33600
#define NV4     8400
#define NCH     56
#define KTOP    3000
#define CAP     4096
#define NB      4096
#define MAXDET  300
#define CONF_T  0.25f
#define IOU_T   0.7f
#define IMGW    1280.0f
#define FULLM   0xFFFFFFFFu
#define BPI2    4
#define CHUNK2  2100    // NV4 / BPI2
#define BPIM    8
#define NSEL    512
#define NW      16      // NSEL / 32
#define LCAPE   336

// ---------------- global scratch (L2-resident) ----------------
__device__ unsigned           g_bstart[BS * NB];     // rewritten by K1 each replay
__device__ unsigned           g_cursor[BS * NB];     // rewritten by K1 each replay
__device__ int                g_cutoff[BS];
__device__ unsigned long long g_keys  [BS * CAP];    // only [bstart,cursor) read
__device__ unsigned long long g_keys2 [BS * CAP];    // fully rewritten each replay
__device__ int                g_ntot  [BS];
__device__ unsigned long long g_k512  [BS * NSEL];
__device__ float4             g_b512  [BS * NSEL];
__device__ float              g_a512  [BS * NSEL];
__device__ unsigned           g_mat   [BS * NSEL * NW];
__device__ unsigned           g_done2 [BS];          // ticket, self-resetting
__device__ unsigned           g_done3 [BS];          // ticket, self-resetting
__device__ int                g_cnt   [BS];
__device__ float4             g_selbox  [BS * MAXDET];
__device__ float              g_selscore[BS * MAXDET];
__device__ int                g_selanch [BS * MAXDET];

__device__ __forceinline__ unsigned ordkey(float f) {
    unsigned b = __float_as_uint(f);
    return (b & 0x80000000u) ? ~b : (b | 0x80000000u);
}
__device__ __forceinline__ float inv_ordkey(unsigned u) {
    unsigned bits = (u & 0x80000000u) ? (u & 0x7FFFFFFFu) : ~u;
    return __uint_as_float(bits);
}
__device__ __forceinline__ int bucket_of(float s) {
    int b = (int)(s * 4096.0f);
    return min(4095, max(0, b));
}
// suppression test, bit-identical to reference rounding (rel_err=0 R1..R14)
__device__ __forceinline__ bool sup_test(float ax, float ay, float az, float aw, float aa,
                                         float bx, float by, float bz, float bw, float ab) {
    float xx1 = fmaxf(ax, bx);
    float yy1 = fmaxf(ay, by);
    float xx2 = fminf(az, bz);
    float yy2 = fminf(aw, bw);
    float ww  = fmaxf(xx2 - xx1, 0.0f);
    float hh  = fmaxf(yy2 - yy1, 0.0f);
    float inter = __fmul_rn(ww, hh);
    if (inter <= 0.0f) return false;
    float denom = __fadd_rn(__fsub_rn(__fadd_rn(aa, ab), inter), 1e-9f);
    return (inter / denom) > IOU_T;
}
__device__ __forceinline__ void decode_box(const float* pimg, unsigned long long key,
                                           float4& b, float& area) {
    int anchor = 65535 - (int)(key & 0xFFFFull);
    anchor = min(anchor, NANCH - 1);
    float cx = pimg[anchor];
    float cy = pimg[(size_t)NANCH + anchor];
    float w  = pimg[2 * (size_t)NANCH + anchor];
    float ht = pimg[3 * (size_t)NANCH + anchor];
    float hw = w * 0.5f, hh = ht * 0.5f;
    b.x = fminf(fmaxf(cx - hw, 0.0f), IMGW);
    b.y = fminf(fmaxf(cy - hh, 0.0f), IMGW);
    b.z = fminf(fmaxf(cx + hw, 0.0f), IMGW);
    b.w = fminf(fmaxf(cy + hh, 0.0f), IMGW);
    area = __fmul_rn(b.z - b.x, b.w - b.y);
}

// ================= K1: hist + suffix scan (one block per image) =================
__global__ void __launch_bounds__(1024) k_scan16(const float* __restrict__ preds) {
    __shared__ unsigned sh[NB];
    __shared__ unsigned wsum[32];
    __shared__ int sb;
    const int img  = blockIdx.x;
    const int tid  = threadIdx.x;
    const int lane = tid & 31;
    const int wid  = tid >> 5;
    const float4* conf4 = (const float4*)(preds + (size_t)img * NCH * NANCH + 4 * (size_t)NANCH);

    ((uint4*)sh)[tid] = make_uint4(0u, 0u, 0u, 0u);
    if (tid == 0) sb = 0;
    __syncthreads();
    for (int i = tid; i < NV4; i += 1024) {
        float4 v = conf4[i];
        if (v.x > CONF_T) atomicAdd(&sh[bucket_of(v.x)], 1u);
        if (v.y > CONF_T) atomicAdd(&sh[bucket_of(v.y)], 1u);
        if (v.z > CONF_T) atomicAdd(&sh[bucket_of(v.z)], 1u);
        if (v.w > CONF_T) atomicAdd(&sh[bucket_of(v.w)], 1u);
    }
    __syncthreads();

    uint4 hv = ((const uint4*)sh)[tid];
    unsigned tot = hv.x + hv.y + hv.z + hv.w;
    unsigned suf = tot;
    #pragma unroll
    for (int d = 1; d < 32; d <<= 1) {
        unsigned v = __shfl_down_sync(FULLM, suf, d);
        if (lane + d < 32) suf += v;
    }
    if (lane == 0) wsum[wid] = suf;
    __syncthreads();
    if (tid < 32) {
        unsigned v  = wsum[tid];
        unsigned sv = v;
        #pragma unroll
        for (int d = 1; d < 32; d <<= 1) {
            unsigned u = __shfl_down_sync(FULLM, sv, d);
            if (tid + d < 32) sv += u;
        }
        wsum[tid] = sv - v;
    }
    __syncthreads();
    unsigned run = wsum[wid] + (suf - tot);
    unsigned e3 = run;
    unsigned e2 = e3 + hv.w;
    unsigned e1 = e2 + hv.z;
    unsigned e0 = e1 + hv.y;
    uint4 ev = make_uint4(e0, e1, e2, e3);
    ((uint4*)(g_bstart + img * NB))[tid] = ev;
    ((uint4*)(g_cursor + img * NB))[tid] = ev;
    if      (e3 + hv.w >= (unsigned)KTOP) atomicMax(&sb, 4 * tid + 3);
    else if (e2 + hv.z >= (unsigned)KTOP) atomicMax(&sb, 4 * tid + 2);
    else if (e1 + hv.y >= (unsigned)KTOP) atomicMax(&sb, 4 * tid + 1);
    else if (e0 + hv.x >= (unsigned)KTOP) atomicMax(&sb, 4 * tid + 0);
    __syncthreads();
    if (tid == 0) g_cutoff[img] = sb;
}

// ================= K2: scatter quarter; last-of-4 ranks + decodes top-512 =================
// smem: bstart 16KB | ends 16KB | raw keys 32KB | sorted keys 32KB = 96KB
#define S2_BST  0
#define S2_END  16384
#define S2_K1   32768
#define S2_K2   65536
#define S2_TOT  98304
__global__ void __launch_bounds__(1024) k_scatrank(const float* __restrict__ preds) {
    extern __shared__ char sm[];
    __shared__ int slast;
    const int img  = blockIdx.x >> 2;
    const int part = blockIdx.x & 3;
    const int tid  = threadIdx.x;
    const float*  pimg  = preds + (size_t)img * NCH * NANCH;
    const float4* conf4 = (const float4*)(pimg + 4 * (size_t)NANCH);
    const int cutoff = g_cutoff[img];

    // ---- scatter own quarter (conf is L2-warm from K1) ----
    {
        unsigned* cursor = g_cursor + img * NB;
        unsigned long long* keysg = g_keys + (size_t)img * CAP;
        const int st = part * CHUNK2;
        const int en = min(NV4, st + CHUNK2);
        for (int i = st + tid; i < en; i += 1024) {
            float4 v = conf4[i];
            float sv[4] = {v.x, v.y, v.z, v.w};
            int a = 4 * i;
            #pragma unroll
            for (int c = 0; c < 4; c++) {
                float s = sv[c];
                if (s > CONF_T) {
                    int b = bucket_of(s);
                    if (b >= cutoff) {
                        unsigned pos = atomicAdd(&cursor[b], 1u);
                        if (pos < CAP)
                            keysg[pos] = ((unsigned long long)ordkey(s) << 16)
                                       | (unsigned)(65535 - (a + c));
                    }
                }
            }
        }
    }
    __syncthreads();
    if (tid == 0) {
        __threadfence();
        slast = (atomicAdd(&g_done2[img], 1u) == BPI2 - 1);
    }
    __syncthreads();
    if (!slast) return;

    // ---- last block: rank + decode top-512 ----
    __threadfence();
    if (tid == 0) g_done2[img] = 0u;

    unsigned*           sbst = (unsigned*)(sm + S2_BST);
    unsigned*           send = (unsigned*)(sm + S2_END);
    unsigned long long* k1   = (unsigned long long*)(sm + S2_K1);
    unsigned long long* k2s  = (unsigned long long*)(sm + S2_K2);

    ((uint4*)sbst)[tid] = ((const uint4*)(g_bstart + img * NB))[tid];
    ((uint4*)send)[tid] = ((const uint4*)(g_cursor + img * NB))[tid];
    for (int r = tid; r < CAP; r += 1024) {
        k1[r]  = g_keys[(size_t)img * CAP + r];
        k2s[r] = 0ull;
    }
    __syncthreads();

    const int ntot = min((int)send[cutoff], CAP);
    for (int p = tid; p < ntot; p += 1024) {
        unsigned long long key = k1[p];
        float sc = inv_ordkey((unsigned)(key >> 16));
        int b   = bucket_of(sc);
        int st2 = (int)sbst[b];
        int en2 = min((int)send[b], CAP);
        int rank = st2;
        for (int q = st2; q < en2; q++) rank += (k1[q] > key) ? 1 : 0;
        k2s[rank] = key;
    }
    __syncthreads();

    for (int r = tid; r < CAP; r += 1024)
        g_keys2[(size_t)img * CAP + r] = k2s[r];
    if (tid < NSEL) {
        unsigned long long key = k2s[tid];
        g_k512[img * NSEL + tid] = key;
        float4 b; float ar;
        decode_box(pimg, key, b, ar);
        g_b512[img * NSEL + tid] = b;
        g_a512[img * NSEL + tid] = ar;
    }
    if (tid == 0) g_ntot[img] = ntot;
}

// ================= K3: parallel 512x512 suppression matrix; last block resolves =================
// smem layout (bytes)
#define M_SBOX  0                        // 512*16 = 8192
#define M_SAREA 8192                     // 512*4  = 2048
#define M_SKEY  10240                    // 512*8  = 4096
#define M_SMAT  14336                    // 512*16*4 = 32768
#define M_LBOX  47104                    // 336*16 = 5376
#define M_LAREA 52480                    // 336*4  = 1344
#define M_LKEY  53824                    // 336*8  = 2688
#define M_TOTAL 56512

__global__ void __launch_bounds__(1024) k_matres(const float* __restrict__ preds) {
    extern __shared__ char sm[];
    float4*             sbox  = (float4*)(sm + M_SBOX);
    float*              sarea = (float*)(sm + M_SAREA);
    unsigned long long* skey  = (unsigned long long*)(sm + M_SKEY);
    unsigned*           smat  = (unsigned*)(sm + M_SMAT);
    float4*             lbox  = (float4*)(sm + M_LBOX);
    float*              slar  = (float*)(sm + M_LAREA);
    unsigned long long* lkey  = (unsigned long long*)(sm + M_LKEY);
    __shared__ unsigned sValid[NW], sSall[NW], sKept0[NW], sK0[NW], sKept[NW], sPref[NW];
    __shared__ int s_cur, slast;

    const int img  = blockIdx.x >> 3;
    const int part = blockIdx.x & 7;
    const int tid  = threadIdx.x;
    const int lane = tid & 31;
    const int w    = tid >> 5;
    const float* pimg = preds + (size_t)img * NCH * NANCH;
    const int ntot = g_ntot[img];

    // ---- load top-512 candidates (coalesced, decoded once in K2) ----
    if (tid < NSEL) {
        skey[tid]  = g_k512[img * NSEL + tid];
        sbox[tid]  = g_b512[img * NSEL + tid];
        sarea[tid] = g_a512[img * NSEL + tid];
    }
    __syncthreads();

    // ---- slab of upper-triangular suppression matrix ----
    {
        const int cw   = w & 15;
        const int half = w >> 4;
        const int j    = cw * 32 + lane;
        float4 bj = sbox[j];
        float  aj = sarea[j];
        const int i0 = part * 64 + half * 32;
        #pragma unroll 4
        for (int r = 0; r < 32; r++) {
            const int i = i0 + r;
            if (cw >= (i >> 5)) {
                float4 bi = sbox[i];
                float  ai = sarea[i];
                bool bit = (j > i) && sup_test(bi.x, bi.y, bi.z, bi.w, ai,
                                               bj.x, bj.y, bj.z, bj.w, aj);
                unsigned bm = __ballot_sync(FULLM, bit);
                if (lane == 0) g_mat[((size_t)img * NSEL + i) * NW + cw] = bm;
            }
        }
    }
    __syncthreads();
    if (tid == 0) {
        __threadfence();
        slast = (atomicAdd(&g_done3[img], 1u) == BPIM - 1);
    }
    __syncthreads();
    if (!slast) return;

    // ---- last block: exact greedy resolve via bit algebra ----
    __threadfence();
    if (tid == 0) { g_done3[img] = 0u; s_cur = 0; }
    for (int idx = tid; idx < NSEL * NW; idx += 1024)
        smat[idx] = g_mat[(size_t)img * NSEL * NW + idx];
    __syncthreads();

    if (w < NW) {
        int c = w * 32 + lane;
        bool valid = (c < ntot) && (skey[c] != 0ull);
        unsigned vb = __ballot_sync(FULLM, valid);
        if (lane == 0) sValid[w] = vb;
    }
    __syncthreads();
    if (w < NW) {
        unsigned acc = 0;
        for (int k = 0; k <= w; k++) {
            int c = k * 32 + lane;
            if ((sValid[k] >> lane) & 1u) acc |= smat[c * NW + w];
        }
        acc = __reduce_or_sync(FULLM, acc);
        if (lane == 0) sSall[w] = acc;
    }
    __syncthreads();
    if (w < NW && lane == 0) sKept0[w] = sValid[w] & ~sSall[w];
    __syncthreads();
    if (w < NW) {
        unsigned acc = 0;
        for (int k = 0; k <= w; k++) {
            int c = k * 32 + lane;
            if ((sKept0[k] >> lane) & 1u) acc |= smat[c * NW + w];
        }
        acc = __reduce_or_sync(FULLM, acc);
        if (lane == 0) sK0[w] = acc;
    }
    __syncthreads();

    if (tid < 32) {
        unsigned Sck = 0;
        unsigned keptReg = 0;
        for (int m = 0; m < NW; m++) {
            unsigned cont = sValid[m] & sSall[m];
            unsigned kc = 0;
            while (cont) {
                int bit = __ffs(cont) - 1;
                cont &= cont - 1u;
                int c = m * 32 + bit;
                unsigned sckm = __shfl_sync(FULLM, Sck, m);
                bool suppressed = (((sK0[m] | sckm) >> bit) & 1u) != 0u;
                if (!suppressed) {
                    kc |= 1u << bit;
                    if (lane < NW && lane >= m) Sck |= smat[c * NW + lane];
                }
            }
            unsigned kw = (sValid[m] & ~sSall[m]) | kc;
            if (lane == m) keptReg = kw;
        }
        int cntw = __popc((lane < NW) ? keptReg : 0u);
        int inc = cntw;
        #pragma unroll
        for (int d = 1; d < 32; d <<= 1) {
            int v = __shfl_up_sync(FULLM, inc, d);
            if (lane >= d) inc += v;
        }
        if (lane < NW) { sKept[lane] = keptReg; sPref[lane] = inc - cntw; }
        if (lane == 31) s_cur = inc;
    }
    __syncthreads();

    if (tid < NSEL) {
        int wrd = tid >> 5;
        int l   = tid & 31;
        unsigned km = sKept[wrd];
        if ((km >> l) & 1u) {
            int rank = (int)sPref[wrd] + __popc(km & ((1u << l) - 1u));
            if (rank < LCAPE) {
                lbox[rank] = sbox[tid];
                slar[rank] = sarea[tid];
                lkey[rank] = skey[tid];
            }
        }
    }
    __syncthreads();

    // exact fallback: continue past NSEL if fewer than MAXDET kept (rare/never)
    if (tid < 32) {
        int curf = s_cur;
        int lim  = min(min(ntot, CAP), KTOP);
        if (curf < MAXDET && lim > NSEL) {
            for (int c = NSEL; c < lim && curf < MAXDET; c++) {
                unsigned long long key = g_keys2[(size_t)img * CAP + c];
                if (key == 0ull) continue;
                float4 bc; float ac;
                decode_box(pimg, key, bc, ac);
                bool sup = false;
                for (int l = lane; l < curf; l += 32) {
                    float4 bl = lbox[l];
                    sup |= sup_test(bl.x, bl.y, bl.z, bl.w, slar[l],
                                    bc.x, bc.y, bc.z, bc.w, ac);
                }
                if (!__any_sync(FULLM, sup)) {
                    if (lane == 0 && curf < LCAPE) {
                        lbox[curf] = bc; slar[curf] = ac; lkey[curf] = key;
                    }
                    __syncwarp();
                    curf++;
                }
            }
        }
        if (lane == 0) s_cur = curf;
    }
    __syncthreads();

    const int cnt = min(s_cur, MAXDET);
    if (tid < cnt) {
        unsigned long long key = lkey[tid];
        g_selbox  [img * MAXDET + tid] = lbox[tid];
        g_selscore[img * MAXDET + tid] = inv_ordkey((unsigned)(key >> 16));
        g_selanch [img * MAXDET + tid] = 65535 - (int)(key & 0xFFFFull);
    }
    if (tid == 0) g_cnt[img] = cnt;
}

// ================= K4: wide output writer =================
#define TOTOUT (BS * MAXDET * 56)
__global__ void __launch_bounds__(1024) k_out(const float* __restrict__ preds,
                                              float* __restrict__ out) {
    int s = blockIdx.x * 1024 + threadIdx.x;
    if (s >= TOTOUT) return;
    const int img = s / (MAXDET * 56);
    const int rem = s % (MAXDET * 56);
    const int r   = rem / 56;
    const int f   = rem % 56;
    const int cnt = g_cnt[img];

    float v = 0.0f;
    if (r < cnt) {
        if (f < 4) {
            float4 b = g_selbox[img * MAXDET + r];
            v = (f == 0) ? b.x : (f == 1) ? b.y : (f == 2) ? b.z : b.w;
        } else if (f == 4) {
            v = g_selscore[img * MAXDET + r];
        } else {
            int c = f - 5;
            int a = g_selanch[img * MAXDET + r];
            v = preds[(size_t)img * NCH * NANCH + (size_t)(5 + c) * NANCH + a];
            if (c < 2) v = fminf(fmaxf(v, 0.0f), IMGW);
        }
    }
    const int OSC = BS * MAXDET * 4;
    const int OKP = OSC + BS * MAXDET;
    if (f < 4)       out[(img * MAXDET + r) * 4 + f] = v;
    else if (f == 4) out[OSC + img * MAXDET + r] = v;
    else             out[OKP + (img * MAXDET + r) * 51 + (f - 5)] = v;
}

// ---------------- launch ----------------
extern "C" void kernel_launch(void* const* d_in, const int* in_sizes, int n_in,
                              void* d_out, int out_size) {
    const float* preds = (const float*)d_in[0];
    float* out = (float*)d_out;
    cudaFuncSetAttribute(k_scatrank, cudaFuncAttributeMaxDynamicSharedMemorySize, S2_TOT);
    cudaFuncSetAttribute(k_matres,   cudaFuncAttributeMaxDynamicSharedMemorySize, M_TOTAL);
    k_scan16  <<<BS, 1024>>>(preds);
    k_scatrank<<<BS * BPI2, 1024, S2_TOT>>>(preds);
    k_matres  <<<BS * BPIM, 1024, M_TOTAL>>>(preds);
    k_out     <<<(TOTOUT + 1023) / 1024, 1024>>>(preds, out);
}